// round 5
// baseline (speedup 1.0000x reference)
#include <cuda_runtime.h>
#include <cuda_fp16.h>

// ---------------------------------------------------------------------------
// N=512, MAX_DIST=16, H=32, N_SPATIAL=64, BOND_TYPES=32.
// edge_sum[i,j,k] = sum_d T[d][edge_input[i,j,d]][k],  T[d] = edge_table @ W[d]
// Round-5 structure (LSU-instruction-bound fix):
//  - T stored as uint2 (2 half2 = 4 k-values) per (d, k2p, e):
//      byte offset = d*2048 + k2p*256 + e*8  -> one LDS.64 per (d, pair, task)
//  - 2 pairs/thread -> STG.64 everywhere (adjacent pairs, same k)
//  - prep kernel packs indices (e*8 per byte) + {sp, rden} aux per pair
//  - full fp16 balanced tree over 16 d, one cvt+FMUL per k
//  - tasks = 512-pair tile x 8 k2p = 4096 over 888 persistent blocks
// ---------------------------------------------------------------------------

#define NN        512
#define PAIRS     (NN * NN)          // 262144
#define MAXD      16
#define H         32
#define NSPAT     64
#define T_WORDS   8192               // 16d * 8k2p * 32e * 2 words = 32KB
#define SHS_U2    512                // 8 k2p * 64 sp uint2 = 4KB
#define SMEM_BYTES (T_WORDS * 4 + SHS_U2 * 8)   // 36864
#define GRID      888                // 6 blocks/SM * 148 SMs
#define N_TASKS   4096               // 512 tiles * 8 k2p

__device__ unsigned g_T[T_WORDS];    // [(d*8+k2p)*32+e] as uint2 words
__device__ uint4    g_packed[PAIRS]; // 16 indices, pre-scaled x8, one byte each
__device__ int2     g_aux[PAIRS];    // {sp, bits(rden)}

static __device__ __forceinline__ unsigned hadd2u(unsigned a, unsigned b) {
    unsigned r;
    asm("add.f16x2 %0, %1, %2;" : "=r"(r) : "r"(a), "r"(b));
    return r;
}
static __device__ __forceinline__ float2 h2f(unsigned u) {
    return __half22float2(*reinterpret_cast<const __half2*>(&u));
}

// Blocks 0..15: compute T[d]. Blocks 16..527: pack indices + aux.
__global__ __launch_bounds__(512)
void prep_kernel(const float* __restrict__ edge_table,
                 const float* __restrict__ W,
                 const int* __restrict__ edge_input,
                 const int* __restrict__ spatial_pos) {
    __shared__ float shE[H * H];   // [h][e]
    __shared__ float shW[H * H];   // [h][k]
    int t = threadIdx.x;

    if (blockIdx.x < MAXD) {
        int d = blockIdx.x;
        for (int i = t; i < H * H; i += 512) {
            int e = i >> 5, h = i & 31;
            shE[h * H + e] = edge_table[i];
            shW[i] = W[d * (H * H) + i];
        }
        __syncthreads();
        int e  = t & 31;
        int k2 = t >> 5;            // 0..15 (half2 index over k)
        float s0 = 0.0f, s1 = 0.0f;
#pragma unroll
        for (int h = 0; h < H; ++h) {
            float ev = shE[h * H + e];
            s0 += ev * shW[h * H + 2 * k2];
            s1 += ev * shW[h * H + 2 * k2 + 1];
        }
        __half2 v = __floats2half2_rn(s0, s1);
        // word index: ((d*8 + k2/2)*32 + e)*2 + (k2&1)
        g_T[((d * 8 + (k2 >> 1)) * 32 + e) * 2 + (k2 & 1)] =
            *reinterpret_cast<unsigned*>(&v);
    } else {
        int pair = (blockIdx.x - MAXD) * 512 + t;   // 512 blocks x 512 = PAIRS
        const int4* ep = (const int4*)edge_input + pair * 4;
        int4 a = ep[0], b = ep[1], c = ep[2], e4 = ep[3];
        uint4 r;
        r.x = ((unsigned)a.x  << 3) | ((unsigned)a.y  << 11) | ((unsigned)a.z  << 19) | ((unsigned)a.w  << 27);
        r.y = ((unsigned)b.x  << 3) | ((unsigned)b.y  << 11) | ((unsigned)b.z  << 19) | ((unsigned)b.w  << 27);
        r.z = ((unsigned)c.x  << 3) | ((unsigned)c.y  << 11) | ((unsigned)c.z  << 19) | ((unsigned)c.w  << 27);
        r.w = ((unsigned)e4.x << 3) | ((unsigned)e4.y << 11) | ((unsigned)e4.z << 19) | ((unsigned)e4.w << 27);
        g_packed[pair] = r;
        int sp = spatial_pos[pair];
        float rden = (sp == 0) ? 1.0f : (1.0f / (float)sp);
        g_aux[pair] = make_int2(sp, __float_as_int(rden));
    }
}

// Gather + fp16 tree for one pair, one k2p task: returns 4 scaled fp32 values.
static __device__ __forceinline__ void gather16(const char* baseT, uint4 pk,
                                                float rden, float out4[4]) {
    unsigned pw[4] = { pk.x, pk.y, pk.z, pk.w };
    unsigned gx[4], gy[4];
#pragma unroll
    for (int g = 0; g < 4; ++g) {       // d = 4g..4g+3
        const char* bg = baseT + g * 8192;
        unsigned w = pw[g];
        uint2 va = *(const uint2*)(bg +        ( w        & 0xFFu));
        uint2 vb = *(const uint2*)(bg + 2048 + ((w >> 8)  & 0xFFu));
        uint2 vc = *(const uint2*)(bg + 4096 + ((w >> 16) & 0xFFu));
        uint2 vd = *(const uint2*)(bg + 6144 + ( w >> 24));
        gx[g] = hadd2u(hadd2u(va.x, vb.x), hadd2u(vc.x, vd.x));
        gy[g] = hadd2u(hadd2u(va.y, vb.y), hadd2u(vc.y, vd.y));
    }
    unsigned sx = hadd2u(hadd2u(gx[0], gx[1]), hadd2u(gx[2], gx[3]));
    unsigned sy = hadd2u(hadd2u(gy[0], gy[1]), hadd2u(gy[2], gy[3]));
    float2 f0 = h2f(sx), f1 = h2f(sy);
    out4[0] = f0.x * rden;
    out4[1] = f0.y * rden;
    out4[2] = f1.x * rden;
    out4[3] = f1.y * rden;
}

__global__ __launch_bounds__(256, 6)
void bond_encoding_kernel(const float* __restrict__ spd_table,
                          float* __restrict__ out) {
    extern __shared__ unsigned sh[];
    unsigned* shT = sh;                     // 8192 words, 32KB
    uint2*    shS = (uint2*)(sh + T_WORDS); // [k2p][sp], 4KB

    {
        const float4* src = (const float4*)g_T;
        float4* dst = (float4*)shT;
#pragma unroll
        for (int i = threadIdx.x; i < T_WORDS / 4; i += 256)
            dst[i] = src[i];
    }
    for (int i = threadIdx.x; i < SHS_U2; i += 256) {
        int k2p = i >> 6;
        int sp  = i & 63;
        __half2 lo = __floats2half2_rn(spd_table[sp * H + 4 * k2p],
                                       spd_table[sp * H + 4 * k2p + 1]);
        __half2 hi = __floats2half2_rn(spd_table[sp * H + 4 * k2p + 2],
                                       spd_table[sp * H + 4 * k2p + 3]);
        shS[i] = make_uint2(*reinterpret_cast<unsigned*>(&lo),
                            *reinterpret_cast<unsigned*>(&hi));
    }
    __syncthreads();

    for (int task = blockIdx.x; task < N_TASKS; task += GRID) {
        int tile = task >> 3;
        int k2p  = task & 7;                     // 4 heads: k = 4*k2p..4*k2p+3
        int pairA = tile * 512 + threadIdx.x * 2;

        const char* baseT = (const char*)shT + k2p * 256;

        uint4 pkA = g_packed[pairA];
        uint4 pkB = g_packed[pairA + 1];
        int4  aux = *((const int4*)g_aux + (pairA >> 1));  // {spA,rdA,spB,rdB}
        float rdA = __int_as_float(aux.y);
        float rdB = __int_as_float(aux.w);

        float eA[4], eB[4];
        gather16(baseT, pkA, rdA, eA);
        gather16(baseT, pkB, rdB, eB);

        int k0 = 4 * k2p;
        float* oe = out + (H + k0) * PAIRS + pairA;
#pragma unroll
        for (int q = 0; q < 4; ++q)
            __stcs((float2*)(oe + q * PAIRS), make_float2(eA[q], eB[q]));

        // phi_spd
        uint2 sA = shS[k2p * NSPAT + aux.x];
        uint2 sB = shS[k2p * NSPAT + aux.z];
        float2 a0 = h2f(sA.x), a1 = h2f(sA.y);
        float2 b0 = h2f(sB.x), b1 = h2f(sB.y);
        float* os = out + k0 * PAIRS + pairA;
        __stcs((float2*)(os + 0 * PAIRS), make_float2(a0.x, b0.x));
        __stcs((float2*)(os + 1 * PAIRS), make_float2(a0.y, b0.y));
        __stcs((float2*)(os + 2 * PAIRS), make_float2(a1.x, b1.x));
        __stcs((float2*)(os + 3 * PAIRS), make_float2(a1.y, b1.y));
    }
}

extern "C" void kernel_launch(void* const* d_in, const int* in_sizes, int n_in,
                              void* d_out, int out_size) {
    const int*   spatial_pos = nullptr;
    const int*   edge_input  = nullptr;
    const float* spd_table   = nullptr;
    const float* edge_table  = nullptr;
    const float* W           = nullptr;
    for (int i = 0; i < n_in; ++i) {
        switch (in_sizes[i]) {
            case PAIRS:          spatial_pos = (const int*)d_in[i];   break;
            case PAIRS * MAXD:   edge_input  = (const int*)d_in[i];   break;
            case NSPAT * H:      spd_table   = (const float*)d_in[i]; break;
            case H * H:          edge_table  = (const float*)d_in[i]; break;
            case NSPAT * H * H:  W           = (const float*)d_in[i]; break;
            default: break;
        }
    }

    prep_kernel<<<MAXD + PAIRS / 512, 512>>>(edge_table, W, edge_input,
                                             spatial_pos);

    cudaFuncSetAttribute(bond_encoding_kernel,
                         cudaFuncAttributeMaxDynamicSharedMemorySize, SMEM_BYTES);
    bond_encoding_kernel<<<GRID, 256, SMEM_BYTES>>>(spd_table, (float*)d_out);
}

// round 6
// speedup vs baseline: 1.2693x; 1.2693x over previous
#include <cuda_runtime.h>
#include <cuda_fp16.h>

// ---------------------------------------------------------------------------
// N=512, MAX_DIST=16, H=32, N_SPATIAL=64, BOND_TYPES=32.
// edge_sum[i,j,k] = sum_d T[d][edge_input[i,j,d]][k],  T[d] = edge_table @ W[d]
// Round-6 = round-4 gather (conflict-free LDS.32 at the crossbar byte floor)
// + dynamic block-level work stealing (atomic counter, ping-pong mailbox)
// + precomputed {sp, 1/sp} aux. Prologue fused: blocks 0..15 compute T[d],
// blocks 16..527 pack indices (e*4 per byte) + aux; block 16 resets counter.
// ---------------------------------------------------------------------------

#define NN        512
#define PAIRS     (NN * NN)          // 262144
#define MAXD      16
#define H         32
#define NSPAT     64
#define T2_ELEMS  (MAXD * 16 * 32)   // 8192 half2 = 32KB
#define SHS_ELEMS (16 * NSPAT)       // 1024 half2 = 4KB
#define SMEM_BYTES ((T2_ELEMS + SHS_ELEMS) * 4)   // 36864
#define GRID      888               // 6 blocks/SM * 148 SMs (single wave)
#define N_TASKS   4096              // 1024 tiles * 4 k-quarters

__device__ __half2   g_T2[T2_ELEMS];
__device__ uint4     g_packed[PAIRS];  // 16 indices, pre-scaled x4, one byte each
__device__ int2      g_aux[PAIRS];     // {sp, bits(1/max(sp,1))}
__device__ unsigned  g_task_counter;

// Blocks 0..15: T[d] precompute. Blocks 16..527: pack + aux. Counter reset.
__global__ __launch_bounds__(512)
void prep_kernel(const float* __restrict__ edge_table,
                 const float* __restrict__ W,
                 const int* __restrict__ edge_input,
                 const int* __restrict__ spatial_pos) {
    __shared__ float shE[H * H];   // [h][e]
    __shared__ float shW[H * H];   // [h][k]
    int t = threadIdx.x;

    if (blockIdx.x < MAXD) {
        int d = blockIdx.x;
        for (int i = t; i < H * H; i += 512) {
            int e = i >> 5, h = i & 31;
            shE[h * H + e] = edge_table[i];
            shW[i] = W[d * (H * H) + i];
        }
        __syncthreads();
        int e  = t & 31;
        int k2 = t >> 5;
        float s0 = 0.0f, s1 = 0.0f;
#pragma unroll
        for (int h = 0; h < H; ++h) {
            float ev = shE[h * H + e];
            s0 += ev * shW[h * H + 2 * k2];
            s1 += ev * shW[h * H + 2 * k2 + 1];
        }
        g_T2[d * 512 + k2 * 32 + e] = __floats2half2_rn(s0, s1);
    } else {
        if (blockIdx.x == MAXD && t == 0) g_task_counter = 0u;
        int pair = (blockIdx.x - MAXD) * 512 + t;
        const int4* ep = (const int4*)edge_input + pair * 4;
        int4 a = ep[0], b = ep[1], c = ep[2], e4 = ep[3];
        uint4 r;
        r.x = ((unsigned)a.x  << 2) | ((unsigned)a.y  << 10) | ((unsigned)a.z  << 18) | ((unsigned)a.w  << 26);
        r.y = ((unsigned)b.x  << 2) | ((unsigned)b.y  << 10) | ((unsigned)b.z  << 18) | ((unsigned)b.w  << 26);
        r.z = ((unsigned)c.x  << 2) | ((unsigned)c.y  << 10) | ((unsigned)c.z  << 18) | ((unsigned)c.w  << 26);
        r.w = ((unsigned)e4.x << 2) | ((unsigned)e4.y << 10) | ((unsigned)e4.z << 18) | ((unsigned)e4.w << 26);
        g_packed[pair] = r;
        int sp = spatial_pos[pair];
        float rden = (sp == 0) ? 1.0f : (1.0f / (float)sp);
        g_aux[pair] = make_int2(sp, __float_as_int(rden));
    }
}

__global__ __launch_bounds__(256, 6)
void bond_encoding_kernel(const float* __restrict__ spd_table,
                          float* __restrict__ out) {
    extern __shared__ float sh[];
    __half2* shT = (__half2*)sh;              // [d][k2][e], 32KB
    __half2* shS = (__half2*)sh + T2_ELEMS;   // [k2][sp],   4KB
    __shared__ int mail[2];

    {
        const float4* src = (const float4*)g_T2;
        float4* dst = (float4*)shT;
#pragma unroll
        for (int i = threadIdx.x; i < T2_ELEMS / 4; i += 256)
            dst[i] = src[i];
    }
    for (int i = threadIdx.x; i < SHS_ELEMS; i += 256) {
        int k2 = i >> 6;
        int sp = i & 63;
        shS[i] = __floats2half2_rn(spd_table[sp * H + 2 * k2],
                                   spd_table[sp * H + 2 * k2 + 1]);
    }
    if (threadIdx.x == 0) mail[0] = (int)atomicAdd(&g_task_counter, 1u);
    __syncthreads();

    int task = mail[0];
    int slot = 1;
    while (task < N_TASKS) {
        // Kick off the fetch for the NEXT task; its latency hides under the
        // current task's compute (consumed only after the trailing barrier).
        if (threadIdx.x == 0) mail[slot] = (int)atomicAdd(&g_task_counter, 1u);

        int tile = task >> 2;
        int kq   = task & 3;                  // k-quarter: 8 heads
        int pair = tile * 256 + threadIdx.x;

        uint4 pk4 = g_packed[pair];           // one LDG.128: all 16 indices *4
        unsigned pk[4] = { pk4.x, pk4.y, pk4.z, pk4.w };
        int2 aux = g_aux[pair];
        float rden = __int_as_float(aux.y);

        float acc[8];
#pragma unroll
        for (int j = 0; j < 8; ++j) acc[j] = 0.0f;

#pragma unroll
        for (int g = 0; g < 4; ++g) {         // d-group of 4: d = 4g..4g+3
            const char* base = (const char*)(shT + ((4 * g) * 16 + kq * 4) * 32);
            unsigned o0 =  pk[g]        & 0xFCu;
            unsigned o1 = (pk[g] >> 8)  & 0xFCu;
            unsigned o2 = (pk[g] >> 16) & 0xFCu;
            unsigned o3 = (pk[g] >> 24);
            const __half2* p0 = (const __half2*)(base          + o0);
            const __half2* p1 = (const __half2*)(base + 2048   + o1);
            const __half2* p2 = (const __half2*)(base + 4096   + o2);
            const __half2* p3 = (const __half2*)(base + 6144   + o3);
#pragma unroll
            for (int j = 0; j < 4; ++j) {     // 4 k2 slots in this quarter
                __half2 tt = __hadd2(__hadd2(p0[j * 32], p1[j * 32]),
                                     __hadd2(p2[j * 32], p3[j * 32]));
                float2 f = __half22float2(tt);
                acc[2 * j]     = fmaf(f.x, rden, acc[2 * j]);
                acc[2 * j + 1] = fmaf(f.y, rden, acc[2 * j + 1]);
            }
        }

        int k0 = kq * 8;
#pragma unroll
        for (int j = 0; j < 4; ++j) {
            float2 sf = __half22float2(shS[(kq * 4 + j) * NSPAT + aux.x]);
            int k = k0 + 2 * j;
            __stcs(out + k * PAIRS + pair,           sf.x);
            __stcs(out + (k + 1) * PAIRS + pair,     sf.y);
            __stcs(out + (H + k) * PAIRS + pair,     acc[2 * j]);
            __stcs(out + (H + k + 1) * PAIRS + pair, acc[2 * j + 1]);
        }

        __syncthreads();       // publishes mail[slot] to the whole block
        task = mail[slot];
        slot ^= 1;
    }
}

extern "C" void kernel_launch(void* const* d_in, const int* in_sizes, int n_in,
                              void* d_out, int out_size) {
    const int*   spatial_pos = nullptr;
    const int*   edge_input  = nullptr;
    const float* spd_table   = nullptr;
    const float* edge_table  = nullptr;
    const float* W           = nullptr;
    for (int i = 0; i < n_in; ++i) {
        switch (in_sizes[i]) {
            case PAIRS:          spatial_pos = (const int*)d_in[i];   break;
            case PAIRS * MAXD:   edge_input  = (const int*)d_in[i];   break;
            case NSPAT * H:      spd_table   = (const float*)d_in[i]; break;
            case H * H:          edge_table  = (const float*)d_in[i]; break;
            case NSPAT * H * H:  W           = (const float*)d_in[i]; break;
            default: break;
        }
    }

    prep_kernel<<<MAXD + PAIRS / 512, 512>>>(edge_table, W, edge_input,
                                             spatial_pos);

    cudaFuncSetAttribute(bond_encoding_kernel,
                         cudaFuncAttributeMaxDynamicSharedMemorySize, SMEM_BYTES);
    bond_encoding_kernel<<<GRID, 256, SMEM_BYTES>>>(spd_table, (float*)d_out);
}